// round 2
// baseline (speedup 1.0000x reference)
#include <cuda_runtime.h>
#include <math.h>

#define Nn   768
#define NNt  (768*768)
#define PROJ 1152
#define CATD 2112

#define RS48 0.14433756729740643f   /* 1/sqrt(48) */
#define RS3  0.5773502691896258f    /* 1/sqrt(3)  */
#define RS54 0.13608276348795434f   /* 1/sqrt(54) */

/* ------------------------- scratch (device globals) ---------------------- */
__device__ float g_Wpack[384 * PROJ];
__device__ float g_bpack[PROJ];
__device__ float g_proj[Nn * PROJ];
__device__ float g_q [Nn * 192];
__device__ float g_k [Nn * 192];
__device__ float g_v [Nn * 192];
__device__ float g_qp[Nn * 144];
__device__ float g_kp[Nn * 144];
__device__ float g_vp[Nn * 288];
__device__ float g_a [(size_t)12 * NNt];     /* logits -> attn (28.3 MB) */
__device__ float g_cat[(size_t)Nn * CATD];

/* ------------------------- K0: pack projection weights ------------------- */
__global__ void k_pack(const float* __restrict__ Wq,  const float* __restrict__ Wkv,
                       const float* __restrict__ Wqp, const float* __restrict__ Wkvp,
                       const float* __restrict__ bq,  const float* __restrict__ bkv,
                       const float* __restrict__ bqp, const float* __restrict__ bkvp)
{
    int idx = blockIdx.x * blockDim.x + threadIdx.x;
    if (idx < 384 * PROJ) {
        int r = idx / PROJ, o = idx % PROJ;
        float v;
        if      (o < 192) v = Wq  [r * 192 + o];
        else if (o < 576) v = Wkv [r * 384 + (o - 192)];
        else if (o < 720) v = Wqp [r * 144 + (o - 576)];
        else              v = Wkvp[r * 432 + (o - 720)];
        g_Wpack[idx] = v;
    }
    if (idx < PROJ) {
        int o = idx;
        float v;
        if      (o < 192) v = bq  [o];
        else if (o < 576) v = bkv [o - 192];
        else if (o < 720) v = bqp [o - 576];
        else              v = bkvp[o - 720];
        g_bpack[o] = v;
    }
}

/* ------------------- K1: projection GEMM 768 x 1152 x 384 ---------------- */
__global__ __launch_bounds__(256) void k_proj_gemm(const float* __restrict__ s)
{
    __shared__ float s_t[16][65];
    __shared__ float w_t[16][64];
    int o0 = blockIdx.x * 64, i0 = blockIdx.y * 64;
    int t  = threadIdx.x;
    int tx = t % 16, ty = t / 16;
    float acc[4][4];
#pragma unroll
    for (int a = 0; a < 4; a++)
#pragma unroll
        for (int b = 0; b < 4; b++) acc[a][b] = 0.f;

    for (int k0 = 0; k0 < 384; k0 += 16) {
        { int ii = t / 4, kc = (t % 4) * 4;
          float4 sv = *(const float4*)&s[(size_t)(i0 + ii) * 384 + k0 + kc];
          s_t[kc + 0][ii] = sv.x; s_t[kc + 1][ii] = sv.y;
          s_t[kc + 2][ii] = sv.z; s_t[kc + 3][ii] = sv.w; }
        { int kc = t / 16, oo = (t % 16) * 4;
          *(float4*)&w_t[kc][oo] =
              *(const float4*)&g_Wpack[(size_t)(k0 + kc) * PROJ + o0 + oo]; }
        __syncthreads();
#pragma unroll
        for (int kc = 0; kc < 16; kc++) {
            float sv[4];
#pragma unroll
            for (int a = 0; a < 4; a++) sv[a] = s_t[kc][ty * 4 + a];
            float4 w4 = *(float4*)&w_t[kc][tx * 4];
            float wv[4] = {w4.x, w4.y, w4.z, w4.w};
#pragma unroll
            for (int a = 0; a < 4; a++)
#pragma unroll
                for (int b = 0; b < 4; b++) acc[a][b] += sv[a] * wv[b];
        }
        __syncthreads();
    }
#pragma unroll
    for (int a = 0; a < 4; a++) {
        float4 o4;
        o4.x = acc[a][0] + g_bpack[o0 + tx * 4 + 0];
        o4.y = acc[a][1] + g_bpack[o0 + tx * 4 + 1];
        o4.z = acc[a][2] + g_bpack[o0 + tx * 4 + 2];
        o4.w = acc[a][3] + g_bpack[o0 + tx * 4 + 3];
        *(float4*)&g_proj[(size_t)(i0 + ty * 4 + a) * PROJ + o0 + tx * 4] = o4;
    }
}

/* -------------- K1b: reshape + rigid-frame rotation of points ------------ */
__global__ __launch_bounds__(192) void k_reshape(const float* __restrict__ rot,
                                                 const float* __restrict__ trans)
{
    int i = blockIdx.x, t = threadIdx.x;
    __shared__ float pr[PROJ];
    for (int idx = t; idx < PROJ; idx += 192) pr[idx] = g_proj[(size_t)i * PROJ + idx];
    __syncthreads();

    g_q[(size_t)i * 192 + t] = pr[t];
    for (int o = t; o < 384; o += 192) {
        int h = o / 32, w = o % 32;
        float v = pr[192 + o];
        if (w < 16) g_k[(size_t)i * 192 + h * 16 + w] = v;
        else        g_v[(size_t)i * 192 + h * 16 + (w - 16)] = v;
    }
    float R0 = rot[i*9+0], R1 = rot[i*9+1], R2 = rot[i*9+2];
    float R3 = rot[i*9+3], R4 = rot[i*9+4], R5 = rot[i*9+5];
    float R6 = rot[i*9+6], R7 = rot[i*9+7], R8 = rot[i*9+8];
    float T0 = trans[i*3+0], T1 = trans[i*3+1], T2 = trans[i*3+2];

    if (t < 48) {
        float v0 = pr[576 + t], v1 = pr[624 + t], v2 = pr[672 + t];
        float x = R0*v0 + R1*v1 + R2*v2 + T0;
        float y = R3*v0 + R4*v1 + R5*v2 + T1;
        float z = R6*v0 + R7*v1 + R8*v2 + T2;
        int base = i * 144 + t * 3;   /* h*4+p == t ; layout [h][p][3] */
        g_qp[base] = x; g_qp[base+1] = y; g_qp[base+2] = z;
    }
    if (t < 144) {
        float v0 = pr[720 + t], v1 = pr[864 + t], v2 = pr[1008 + t];
        float x = R0*v0 + R1*v1 + R2*v2 + T0;
        float y = R3*v0 + R4*v1 + R5*v2 + T1;
        float z = R6*v0 + R7*v1 + R8*v2 + T2;
        int h = t / 12, r = t % 12;
        if (r < 4) {
            int base = i * 144 + (h * 4 + r) * 3;
            g_kp[base] = x; g_kp[base+1] = y; g_kp[base+2] = z;
        } else {
            int base = i * 288 + (h * 8 + (r - 4)) * 3;
            g_vp[base] = x; g_vp[base+1] = y; g_vp[base+2] = z;
        }
    }
}

/* ---- K2a: logits = qk*rs48 + pt + mask + rs3*b_b   (64x64xh tiles) ------ */
__global__ __launch_bounds__(256) void k_logits(const float* __restrict__ mask,
                                                const float* __restrict__ hwraw,
                                                const float* __restrict__ b_b)
{
    __shared__ float q_sT[16][64], k_sT[16][64];
    __shared__ float qp_sT[12][64], kp_sT[12][64];
    __shared__ float mi_s[64], mj_s[64];
    __shared__ float hw_sh, bb_sh;
    int h = blockIdx.z, i0 = blockIdx.y * 64, j0 = blockIdx.x * 64;
    int t = threadIdx.x;

    { int ii = t / 4, c0 = (t % 4) * 4;
      float4 qv = *(const float4*)&g_q[(size_t)(i0 + ii) * 192 + h * 16 + c0];
      q_sT[c0+0][ii] = qv.x; q_sT[c0+1][ii] = qv.y; q_sT[c0+2][ii] = qv.z; q_sT[c0+3][ii] = qv.w;
      float4 kv = *(const float4*)&g_k[(size_t)(j0 + ii) * 192 + h * 16 + c0];
      k_sT[c0+0][ii] = kv.x; k_sT[c0+1][ii] = kv.y; k_sT[c0+2][ii] = kv.z; k_sT[c0+3][ii] = kv.w; }
    if (t < 192) {
      int ii = t / 3, c0 = (t % 3) * 4;
      float4 qv = *(const float4*)&g_qp[(size_t)(i0 + ii) * 144 + h * 12 + c0];
      qp_sT[c0+0][ii] = qv.x; qp_sT[c0+1][ii] = qv.y; qp_sT[c0+2][ii] = qv.z; qp_sT[c0+3][ii] = qv.w;
      float4 kv = *(const float4*)&g_kp[(size_t)(j0 + ii) * 144 + h * 12 + c0];
      kp_sT[c0+0][ii] = kv.x; kp_sT[c0+1][ii] = kv.y; kp_sT[c0+2][ii] = kv.z; kp_sT[c0+3][ii] = kv.w; }
    if (t < 64) { mi_s[t] = mask[i0 + t]; mj_s[t] = mask[j0 + t]; }
    if (t == 0) {
        hw_sh = log1pf(expf(hwraw[h])) * RS54;
        bb_sh = b_b[h] * RS3;
    }
    __syncthreads();

    int tx = t % 16, ty = t / 16;
    float acc[4][4], d2[4][4];
#pragma unroll
    for (int a = 0; a < 4; a++)
#pragma unroll
        for (int b = 0; b < 4; b++) { acc[a][b] = 0.f; d2[a][b] = 0.f; }

#pragma unroll
    for (int c = 0; c < 16; c++) {
        float qr[4];
#pragma unroll
        for (int a = 0; a < 4; a++) qr[a] = q_sT[c][ty * 4 + a];
        float4 k4 = *(float4*)&k_sT[c][tx * 4];
        float kr[4] = {k4.x, k4.y, k4.z, k4.w};
#pragma unroll
        for (int a = 0; a < 4; a++)
#pragma unroll
            for (int b = 0; b < 4; b++) acc[a][b] += qr[a] * kr[b];
    }
#pragma unroll
    for (int p = 0; p < 4; p++) {
        float qx[4], qy[4], qz[4], kx[4], ky[4], kz[4];
#pragma unroll
        for (int a = 0; a < 4; a++) {
            qx[a] = qp_sT[p*3+0][ty*4+a];
            qy[a] = qp_sT[p*3+1][ty*4+a];
            qz[a] = qp_sT[p*3+2][ty*4+a];
        }
#pragma unroll
        for (int b = 0; b < 4; b++) {
            kx[b] = kp_sT[p*3+0][tx*4+b];
            ky[b] = kp_sT[p*3+1][tx*4+b];
            kz[b] = kp_sT[p*3+2][tx*4+b];
        }
#pragma unroll
        for (int a = 0; a < 4; a++)
#pragma unroll
            for (int b = 0; b < 4; b++) {
                float dx = qx[a]-kx[b], dy = qy[a]-ky[b], dz = qz[a]-kz[b];
                d2[a][b] += dx*dx + dy*dy + dz*dz;
            }
    }
    float hw = hw_sh, bb = bb_sh;
#pragma unroll
    for (int a = 0; a < 4; a++) {
        float mi = mi_s[ty * 4 + a];
        float4 o4;
        o4.x = acc[a][0]*RS48 - 0.5f*hw*d2[a][0] + bb + 100000.0f*(mi*mj_s[tx*4+0] - 1.0f);
        o4.y = acc[a][1]*RS48 - 0.5f*hw*d2[a][1] + bb + 100000.0f*(mi*mj_s[tx*4+1] - 1.0f);
        o4.z = acc[a][2]*RS48 - 0.5f*hw*d2[a][2] + bb + 100000.0f*(mi*mj_s[tx*4+2] - 1.0f);
        o4.w = acc[a][3]*RS48 - 0.5f*hw*d2[a][3] + bb + 100000.0f*(mi*mj_s[tx*4+3] - 1.0f);
        *(float4*)&g_a[(size_t)h * NNt + (size_t)(i0 + ty*4 + a) * Nn + j0 + tx*4] = o4;
    }
}

/* ------------- K2b: logits += rs3 * (z @ W_b)  (z read #1) --------------- */
__global__ __launch_bounds__(128) void k_bias_add(const float* __restrict__ z,
                                                  const float* __restrict__ W_b)
{
    __shared__ float z_s[256 * 17];
    __shared__ float wb_s[128 * 12];
    int i = blockIdx.y, j0 = blockIdx.x * 256;
    int t = threadIdx.x;
    for (int idx = t; idx < 1536; idx += 128) wb_s[idx] = W_b[idx];

    int hg = t & 1, jg = t >> 1;
    float acc[4][6];
#pragma unroll
    for (int k = 0; k < 4; k++)
#pragma unroll
        for (int hh = 0; hh < 6; hh++) acc[k][hh] = 0.f;

    const float* zrow = z + (size_t)i * (Nn * 128);
    for (int cc = 0; cc < 8; cc++) {
        __syncthreads();
#pragma unroll
        for (int k = 0; k < 8; k++) {
            int f = t + k * 128;
            int jj = f >> 2, c4 = (f & 3) * 4;
            float4 zv = *(const float4*)&zrow[(size_t)(j0 + jj) * 128 + cc * 16 + c4];
            z_s[jj*17+c4+0] = zv.x; z_s[jj*17+c4+1] = zv.y;
            z_s[jj*17+c4+2] = zv.z; z_s[jj*17+c4+3] = zv.w;
        }
        __syncthreads();
#pragma unroll
        for (int c = 0; c < 16; c++) {
            float wv[6];
#pragma unroll
            for (int hh = 0; hh < 6; hh++) wv[hh] = wb_s[(cc*16+c)*12 + hg*6 + hh];
#pragma unroll
            for (int k = 0; k < 4; k++) {
                float zr = z_s[(jg*4+k)*17 + c];
#pragma unroll
                for (int hh = 0; hh < 6; hh++) acc[k][hh] += zr * wv[hh];
            }
        }
    }
#pragma unroll
    for (int hh = 0; hh < 6; hh++) {
        int h = hg * 6 + hh;
        float* ap = &g_a[(size_t)h * NNt + (size_t)i * Nn + j0 + jg*4];
        float4 v = *(float4*)ap;
        v.x += RS3 * acc[0][hh]; v.y += RS3 * acc[1][hh];
        v.z += RS3 * acc[2][hh]; v.w += RS3 * acc[3][hh];
        *(float4*)ap = v;
    }
}

/* ------------- K3: weighted softmax over j per (h, i) row ---------------- */
__global__ __launch_bounds__(256) void k_softmax(const float* __restrict__ ss)
{
    int i = blockIdx.x, h = blockIdx.y, t = threadIdx.x;
    float* row = &g_a[(size_t)h * NNt + (size_t)i * Nn];
    __shared__ float rbuf[8];
    __shared__ float mshared, sshared;

    float v[3], m = -1e30f;
#pragma unroll
    for (int k = 0; k < 3; k++) { v[k] = row[t + k*256]; m = fmaxf(m, v[k]); }
#pragma unroll
    for (int o = 16; o; o >>= 1) m = fmaxf(m, __shfl_xor_sync(0xffffffffu, m, o));
    if ((t & 31) == 0) rbuf[t >> 5] = m;
    __syncthreads();
    if (t == 0) {
        float mm = rbuf[0];
#pragma unroll
        for (int w = 1; w < 8; w++) mm = fmaxf(mm, rbuf[w]);
        mshared = mm;
    }
    __syncthreads();
    m = mshared;

    float e[3], lsum = 0.f;
#pragma unroll
    for (int k = 0; k < 3; k++) {
        float w = expf(ss[(size_t)i * Nn + t + k*256]) - 0.99f;
        e[k] = expf(v[k] - m) * w;
        lsum += e[k];
    }
#pragma unroll
    for (int o = 16; o; o >>= 1) lsum += __shfl_xor_sync(0xffffffffu, lsum, o);
    __syncthreads();
    if ((t & 31) == 0) rbuf[t >> 5] = lsum;
    __syncthreads();
    if (t == 0) {
        float sm = 0.f;
#pragma unroll
        for (int w = 0; w < 8; w++) sm += rbuf[w];
        sshared = sm;
    }
    __syncthreads();
    float inv = 1.0f / sshared;
#pragma unroll
    for (int k = 0; k < 3; k++) row[t + k*256] = e[k] * inv;
}

/* ------ K4: o = a.v ; o_pt = R^T(a.vp - T), norms   (one block per i) ---- */
__global__ __launch_bounds__(256) void k_out_ov(const float* __restrict__ rot,
                                                const float* __restrict__ trans)
{
    __shared__ float a_s[12 * 16];
    __shared__ float v_s[16 * 192];
    __shared__ float vp_s[16 * 288];
    __shared__ float pt_s[288];
    int i = blockIdx.x, t = threadIdx.x;
    /* 480 outputs: f = h*40 + w ; w<16 -> o[h][w], else pt[h][w-16] */
    int f0 = t, f1 = t + 240;
    int h0 = f0 / 40, w0 = f0 % 40;
    int h1 = f1 / 40, w1 = f1 % 40;
    float acc0 = 0.f, acc1 = 0.f;

    for (int j0 = 0; j0 < Nn; j0 += 16) {
        __syncthreads();
        if (t < 192) { int hh = t / 16, jj = t % 16;
            a_s[hh*16+jj] = g_a[(size_t)hh * NNt + (size_t)i * Nn + j0 + jj]; }
        for (int idx = t; idx < 16*192; idx += 256)
            v_s[idx] = g_v[(size_t)j0 * 192 + idx];
        for (int idx = t; idx < 16*288; idx += 256)
            vp_s[idx] = g_vp[(size_t)j0 * 288 + idx];
        __syncthreads();
        if (t < 240) {
#pragma unroll
            for (int jj = 0; jj < 16; jj++) {
                float s0 = (w0 < 16) ? v_s[jj*192 + h0*16 + w0]
                                     : vp_s[jj*288 + h0*24 + (w0-16)];
                float s1 = (w1 < 16) ? v_s[jj*192 + h1*16 + w1]
                                     : vp_s[jj*288 + h1*24 + (w1-16)];
                acc0 += a_s[h0*16+jj] * s0;
                acc1 += a_s[h1*16+jj] * s1;
            }
        }
    }
    __syncthreads();
    if (t < 240) {
        if (w0 < 16) g_cat[(size_t)i * CATD + h0*16 + w0] = acc0;
        else         pt_s[h0*24 + (w0-16)] = acc0;
        if (w1 < 16) g_cat[(size_t)i * CATD + h1*16 + w1] = acc1;
        else         pt_s[h1*24 + (w1-16)] = acc1;
    }
    __syncthreads();
    if (t < 96) {
        int h = t / 8, p = t % 8;
        float gx = pt_s[h*24 + p*3 + 0] - trans[i*3+0];
        float gy = pt_s[h*24 + p*3 + 1] - trans[i*3+1];
        float gz = pt_s[h*24 + p*3 + 2] - trans[i*3+2];
        const float* R = &rot[i*9];
        float lx = R[0]*gx + R[3]*gy + R[6]*gz;
        float ly = R[1]*gx + R[4]*gy + R[7]*gz;
        float lz = R[2]*gx + R[5]*gy + R[8]*gz;
        float nrm = sqrtf(lx*lx + ly*ly + lz*lz + 1e-8f);
        size_t base = (size_t)i * CATD;
        int hp = h*8 + p;
        g_cat[base + 192 + hp] = lx;
        g_cat[base + 288 + hp] = ly;
        g_cat[base + 384 + hp] = lz;
        g_cat[base + 480 + hp] = nrm;
    }
}

/* -------- K5: o_pair = a . z   (z read #2, one block per i) -------------- */
__global__ __launch_bounds__(256) void k_opair(const float* __restrict__ z)
{
    __shared__ float a_s[12 * Nn];   /* 36 KB */
    int i = blockIdx.x, t = threadIdx.x;
    for (int idx = t; idx < 12 * Nn; idx += 256) {
        int h = idx / Nn, j = idx % Nn;
        a_s[idx] = g_a[(size_t)h * NNt + (size_t)i * Nn + j];
    }
    __syncthreads();

    int c = t & 127, hg = t >> 7;            /* hg in {0,1} -> 6 heads each */
    const float* zr = z + (size_t)i * Nn * 128 + c;
    const float* ap = &a_s[hg * 6 * Nn];
    float acc[6] = {0.f, 0.f, 0.f, 0.f, 0.f, 0.f};
#pragma unroll 4
    for (int j = 0; j < Nn; j++) {
        float zv = __ldg(zr + (size_t)j * 128);
#pragma unroll
        for (int k = 0; k < 6; k++) acc[k] += ap[k * Nn + j] * zv;
    }
    size_t base = (size_t)i * CATD + 576;
#pragma unroll
    for (int k = 0; k < 6; k++)
        g_cat[base + (hg*6 + k) * 128 + c] = acc[k];
}

/* ------------------- K6: final GEMM 768 x 384 x 2112 --------------------- */
__global__ __launch_bounds__(256) void k_final(float* __restrict__ out,
                                               const float* __restrict__ W_out,
                                               const float* __restrict__ b_out)
{
    __shared__ float c_t[16][65];
    __shared__ float w_t[16][64];
    int o0 = blockIdx.x * 64, i0 = blockIdx.y * 64;
    int t = threadIdx.x;
    int tx = t % 16, ty = t / 16;
    float acc[4][4];
#pragma unroll
    for (int a = 0; a < 4; a++)
#pragma unroll
        for (int b = 0; b < 4; b++) acc[a][b] = 0.f;

    for (int k0 = 0; k0 < CATD; k0 += 16) {
        { int ii = t / 4, kc = (t % 4) * 4;
          float4 cv = *(const float4*)&g_cat[(size_t)(i0 + ii) * CATD + k0 + kc];
          c_t[kc+0][ii] = cv.x; c_t[kc+1][ii] = cv.y;
          c_t[kc+2][ii] = cv.z; c_t[kc+3][ii] = cv.w; }
        { int kc = t / 16, oo = (t % 16) * 4;
          *(float4*)&w_t[kc][oo] =
              *(const float4*)&W_out[(size_t)(k0 + kc) * 384 + o0 + oo]; }
        __syncthreads();
#pragma unroll
        for (int kc = 0; kc < 16; kc++) {
            float cv[4];
#pragma unroll
            for (int a = 0; a < 4; a++) cv[a] = c_t[kc][ty*4+a];
            float4 w4 = *(float4*)&w_t[kc][tx*4];
            float wv[4] = {w4.x, w4.y, w4.z, w4.w};
#pragma unroll
            for (int a = 0; a < 4; a++)
#pragma unroll
                for (int b = 0; b < 4; b++) acc[a][b] += cv[a] * wv[b];
        }
        __syncthreads();
    }
#pragma unroll
    for (int a = 0; a < 4; a++) {
        float4 o4;
        o4.x = acc[a][0] + b_out[o0 + tx*4 + 0];
        o4.y = acc[a][1] + b_out[o0 + tx*4 + 1];
        o4.z = acc[a][2] + b_out[o0 + tx*4 + 2];
        o4.w = acc[a][3] + b_out[o0 + tx*4 + 3];
        *(float4*)&out[(size_t)(i0 + ty*4 + a) * 384 + o0 + tx*4] = o4;
    }
}

/* ------------------------------- launch ---------------------------------- */
extern "C" void kernel_launch(void* const* d_in, const int* in_sizes, int n_in,
                              void* d_out, int out_size)
{
    const float* s     = (const float*)d_in[0];
    const float* z     = (const float*)d_in[1];
    const float* rot   = (const float*)d_in[2];
    const float* trans = (const float*)d_in[3];
    const float* mask  = (const float*)d_in[4];
    const float* ss    = (const float*)d_in[5];
    const float* W_q   = (const float*)d_in[6];
    const float* b_q   = (const float*)d_in[7];
    const float* W_kv  = (const float*)d_in[8];
    const float* b_kv  = (const float*)d_in[9];
    const float* W_qp  = (const float*)d_in[10];
    const float* b_qp  = (const float*)d_in[11];
    const float* W_kvp = (const float*)d_in[12];
    const float* b_kvp = (const float*)d_in[13];
    const float* W_b   = (const float*)d_in[14];
    const float* b_b   = (const float*)d_in[15];
    const float* hwts  = (const float*)d_in[16];
    const float* W_out = (const float*)d_in[17];
    const float* b_out = (const float*)d_in[18];
    float* out = (float*)d_out;

    k_pack<<<(384 * PROJ + 255) / 256, 256>>>(W_q, W_kv, W_qp, W_kvp,
                                              b_q, b_kv, b_qp, b_kvp);
    { dim3 g(PROJ / 64, Nn / 64); k_proj_gemm<<<g, 256>>>(s); }
    k_reshape<<<Nn, 192>>>(rot, trans);
    { dim3 g(Nn / 64, Nn / 64, 12); k_logits<<<g, 256>>>(mask, hwts, b_b); }
    { dim3 g(Nn / 256, Nn); k_bias_add<<<g, 128>>>(z, W_b); }
    { dim3 g(Nn, 12); k_softmax<<<g, 256>>>(ss); }
    k_out_ov<<<Nn, 256>>>(rot, trans);
    k_opair<<<Nn, 256>>>(z);
    { dim3 g(384 / 64, Nn / 64); k_final<<<g, 256>>>(out, W_out, b_out); }
}

// round 3
// speedup vs baseline: 1.1072x; 1.1072x over previous
#include <cuda_runtime.h>
#include <math.h>

#define Nn   768
#define NNt  (768*768)
#define PROJ 1152
#define CATD 2112

#define RS48 0.14433756729740643f   /* 1/sqrt(48) */
#define RS3  0.5773502691896258f    /* 1/sqrt(3)  */
#define RS54 0.13608276348795434f   /* 1/sqrt(54) */

/* ------------------------- scratch (device globals) ---------------------- */
__device__ float g_Wpack[384 * PROJ];
__device__ float g_bpack[PROJ];
__device__ float g_proj[Nn * PROJ];
__device__ float g_q [Nn * 192];
__device__ float g_k [Nn * 192];
__device__ float g_qp[Nn * 144];
__device__ float g_kp[Nn * 144];
__device__ float g_vc[12 * Nn * 48];        /* packed v(16) || vp(24) per (h,j) */
__device__ float g_a [(size_t)12 * NNt];    /* logits -> attn (28.3 MB) */
__device__ float g_ptg[Nn * 12 * 24];       /* o_pt in global frame */
__device__ float g_cat[(size_t)Nn * CATD];

/* ------------------------- K0: pack projection weights ------------------- */
__global__ void k_pack(const float* __restrict__ Wq,  const float* __restrict__ Wkv,
                       const float* __restrict__ Wqp, const float* __restrict__ Wkvp,
                       const float* __restrict__ bq,  const float* __restrict__ bkv,
                       const float* __restrict__ bqp, const float* __restrict__ bkvp)
{
    int idx = blockIdx.x * blockDim.x + threadIdx.x;
    if (idx < 384 * PROJ) {
        int r = idx / PROJ, o = idx % PROJ;
        float v;
        if      (o < 192) v = Wq  [r * 192 + o];
        else if (o < 576) v = Wkv [r * 384 + (o - 192)];
        else if (o < 720) v = Wqp [r * 144 + (o - 576)];
        else              v = Wkvp[r * 432 + (o - 720)];
        g_Wpack[idx] = v;
    }
    if (idx < PROJ) {
        int o = idx;
        float v;
        if      (o < 192) v = bq  [o];
        else if (o < 576) v = bkv [o - 192];
        else if (o < 720) v = bqp [o - 576];
        else              v = bkvp[o - 720];
        g_bpack[o] = v;
    }
}

/* ------------------- K1: projection GEMM 768 x 1152 x 384 ---------------- */
__global__ __launch_bounds__(256) void k_proj_gemm(const float* __restrict__ s)
{
    __shared__ float s_t[16][65];
    __shared__ float w_t[16][64];
    int o0 = blockIdx.x * 64, i0 = blockIdx.y * 64;
    int t  = threadIdx.x;
    int tx = t % 16, ty = t / 16;
    float acc[4][4];
#pragma unroll
    for (int a = 0; a < 4; a++)
#pragma unroll
        for (int b = 0; b < 4; b++) acc[a][b] = 0.f;

    for (int k0 = 0; k0 < 384; k0 += 16) {
        { int ii = t / 4, kc = (t % 4) * 4;
          float4 sv = *(const float4*)&s[(size_t)(i0 + ii) * 384 + k0 + kc];
          s_t[kc + 0][ii] = sv.x; s_t[kc + 1][ii] = sv.y;
          s_t[kc + 2][ii] = sv.z; s_t[kc + 3][ii] = sv.w; }
        { int kc = t / 16, oo = (t % 16) * 4;
          *(float4*)&w_t[kc][oo] =
              *(const float4*)&g_Wpack[(size_t)(k0 + kc) * PROJ + o0 + oo]; }
        __syncthreads();
#pragma unroll
        for (int kc = 0; kc < 16; kc++) {
            float sv[4];
#pragma unroll
            for (int a = 0; a < 4; a++) sv[a] = s_t[kc][ty * 4 + a];
            float4 w4 = *(float4*)&w_t[kc][tx * 4];
            float wv[4] = {w4.x, w4.y, w4.z, w4.w};
#pragma unroll
            for (int a = 0; a < 4; a++)
#pragma unroll
                for (int b = 0; b < 4; b++) acc[a][b] += sv[a] * wv[b];
        }
        __syncthreads();
    }
#pragma unroll
    for (int a = 0; a < 4; a++) {
        float4 o4;
        o4.x = acc[a][0] + g_bpack[o0 + tx * 4 + 0];
        o4.y = acc[a][1] + g_bpack[o0 + tx * 4 + 1];
        o4.z = acc[a][2] + g_bpack[o0 + tx * 4 + 2];
        o4.w = acc[a][3] + g_bpack[o0 + tx * 4 + 3];
        *(float4*)&g_proj[(size_t)(i0 + ty * 4 + a) * PROJ + o0 + tx * 4] = o4;
    }
}

/* -------------- K1b: reshape + rigid-frame rotation of points ------------ */
__global__ __launch_bounds__(192) void k_reshape(const float* __restrict__ rot,
                                                 const float* __restrict__ trans)
{
    int i = blockIdx.x, t = threadIdx.x;
    __shared__ float pr[PROJ];
    for (int idx = t; idx < PROJ; idx += 192) pr[idx] = g_proj[(size_t)i * PROJ + idx];
    __syncthreads();

    g_q[(size_t)i * 192 + t] = pr[t];
    for (int o = t; o < 384; o += 192) {
        int h = o / 32, w = o % 32;
        float v = pr[192 + o];
        if (w < 16) g_k[(size_t)i * 192 + h * 16 + w] = v;
        else        g_vc[(size_t)(h * Nn + i) * 48 + (w - 16)] = v;
    }
    float R0 = rot[i*9+0], R1 = rot[i*9+1], R2 = rot[i*9+2];
    float R3 = rot[i*9+3], R4 = rot[i*9+4], R5 = rot[i*9+5];
    float R6 = rot[i*9+6], R7 = rot[i*9+7], R8 = rot[i*9+8];
    float T0 = trans[i*3+0], T1 = trans[i*3+1], T2 = trans[i*3+2];

    if (t < 48) {
        float v0 = pr[576 + t], v1 = pr[624 + t], v2 = pr[672 + t];
        float x = R0*v0 + R1*v1 + R2*v2 + T0;
        float y = R3*v0 + R4*v1 + R5*v2 + T1;
        float z = R6*v0 + R7*v1 + R8*v2 + T2;
        int base = i * 144 + t * 3;
        g_qp[base] = x; g_qp[base+1] = y; g_qp[base+2] = z;
    }
    if (t < 144) {
        float v0 = pr[720 + t], v1 = pr[864 + t], v2 = pr[1008 + t];
        float x = R0*v0 + R1*v1 + R2*v2 + T0;
        float y = R3*v0 + R4*v1 + R5*v2 + T1;
        float z = R6*v0 + R7*v1 + R8*v2 + T2;
        int h = t / 12, r = t % 12;
        if (r < 4) {
            int base = i * 144 + (h * 4 + r) * 3;
            g_kp[base] = x; g_kp[base+1] = y; g_kp[base+2] = z;
        } else {
            int base = (h * Nn + i) * 48 + 16 + (r - 4) * 3;
            g_vc[base] = x; g_vc[base+1] = y; g_vc[base+2] = z;
        }
    }
}

/* ---- K2a: logits = qk*rs48 + pt + mask + rs3*b_b   (64x64xh tiles) ------ */
__global__ __launch_bounds__(256) void k_logits(const float* __restrict__ mask,
                                                const float* __restrict__ hwraw,
                                                const float* __restrict__ b_b)
{
    __shared__ float q_sT[16][64], k_sT[16][64];
    __shared__ float qp_sT[12][64], kp_sT[12][64];
    __shared__ float mi_s[64], mj_s[64];
    __shared__ float hw_sh, bb_sh;
    int h = blockIdx.z, i0 = blockIdx.y * 64, j0 = blockIdx.x * 64;
    int t = threadIdx.x;

    { int ii = t / 4, c0 = (t % 4) * 4;
      float4 qv = *(const float4*)&g_q[(size_t)(i0 + ii) * 192 + h * 16 + c0];
      q_sT[c0+0][ii] = qv.x; q_sT[c0+1][ii] = qv.y; q_sT[c0+2][ii] = qv.z; q_sT[c0+3][ii] = qv.w;
      float4 kv = *(const float4*)&g_k[(size_t)(j0 + ii) * 192 + h * 16 + c0];
      k_sT[c0+0][ii] = kv.x; k_sT[c0+1][ii] = kv.y; k_sT[c0+2][ii] = kv.z; k_sT[c0+3][ii] = kv.w; }
    if (t < 192) {
      int ii = t / 3, c0 = (t % 3) * 4;
      float4 qv = *(const float4*)&g_qp[(size_t)(i0 + ii) * 144 + h * 12 + c0];
      qp_sT[c0+0][ii] = qv.x; qp_sT[c0+1][ii] = qv.y; qp_sT[c0+2][ii] = qv.z; qp_sT[c0+3][ii] = qv.w;
      float4 kv = *(const float4*)&g_kp[(size_t)(j0 + ii) * 144 + h * 12 + c0];
      kp_sT[c0+0][ii] = kv.x; kp_sT[c0+1][ii] = kv.y; kp_sT[c0+2][ii] = kv.z; kp_sT[c0+3][ii] = kv.w; }
    if (t < 64) { mi_s[t] = mask[i0 + t]; mj_s[t] = mask[j0 + t]; }
    if (t == 0) {
        hw_sh = log1pf(expf(hwraw[h])) * RS54;
        bb_sh = b_b[h] * RS3;
    }
    __syncthreads();

    int tx = t % 16, ty = t / 16;
    float acc[4][4], d2[4][4];
#pragma unroll
    for (int a = 0; a < 4; a++)
#pragma unroll
        for (int b = 0; b < 4; b++) { acc[a][b] = 0.f; d2[a][b] = 0.f; }

#pragma unroll
    for (int c = 0; c < 16; c++) {
        float qr[4];
#pragma unroll
        for (int a = 0; a < 4; a++) qr[a] = q_sT[c][ty * 4 + a];
        float4 k4 = *(float4*)&k_sT[c][tx * 4];
        float kr[4] = {k4.x, k4.y, k4.z, k4.w};
#pragma unroll
        for (int a = 0; a < 4; a++)
#pragma unroll
            for (int b = 0; b < 4; b++) acc[a][b] += qr[a] * kr[b];
    }
#pragma unroll
    for (int p = 0; p < 4; p++) {
        float qx[4], qy[4], qz[4], kx[4], ky[4], kz[4];
#pragma unroll
        for (int a = 0; a < 4; a++) {
            qx[a] = qp_sT[p*3+0][ty*4+a];
            qy[a] = qp_sT[p*3+1][ty*4+a];
            qz[a] = qp_sT[p*3+2][ty*4+a];
        }
#pragma unroll
        for (int b = 0; b < 4; b++) {
            kx[b] = kp_sT[p*3+0][tx*4+b];
            ky[b] = kp_sT[p*3+1][tx*4+b];
            kz[b] = kp_sT[p*3+2][tx*4+b];
        }
#pragma unroll
        for (int a = 0; a < 4; a++)
#pragma unroll
            for (int b = 0; b < 4; b++) {
                float dx = qx[a]-kx[b], dy = qy[a]-ky[b], dz = qz[a]-kz[b];
                d2[a][b] += dx*dx + dy*dy + dz*dz;
            }
    }
    float hw = hw_sh, bb = bb_sh;
#pragma unroll
    for (int a = 0; a < 4; a++) {
        float mi = mi_s[ty * 4 + a];
        float4 o4;
        o4.x = acc[a][0]*RS48 - 0.5f*hw*d2[a][0] + bb + 100000.0f*(mi*mj_s[tx*4+0] - 1.0f);
        o4.y = acc[a][1]*RS48 - 0.5f*hw*d2[a][1] + bb + 100000.0f*(mi*mj_s[tx*4+1] - 1.0f);
        o4.z = acc[a][2]*RS48 - 0.5f*hw*d2[a][2] + bb + 100000.0f*(mi*mj_s[tx*4+2] - 1.0f);
        o4.w = acc[a][3]*RS48 - 0.5f*hw*d2[a][3] + bb + 100000.0f*(mi*mj_s[tx*4+3] - 1.0f);
        *(float4*)&g_a[(size_t)h * NNt + (size_t)(i0 + ty*4 + a) * Nn + j0 + tx*4] = o4;
    }
}

/* ------------- K2b: logits += rs3 * (z @ W_b)  (z read #1) --------------- */
__global__ __launch_bounds__(128) void k_bias_add(const float* __restrict__ z,
                                                  const float* __restrict__ W_b)
{
    __shared__ float z_s[256 * 17];
    __shared__ float wb_s[128 * 12];
    int i = blockIdx.y, j0 = blockIdx.x * 256;
    int t = threadIdx.x;
    for (int idx = t; idx < 1536; idx += 128) wb_s[idx] = W_b[idx];

    int hg = t & 1, jg = t >> 1;
    float acc[4][6];
#pragma unroll
    for (int k = 0; k < 4; k++)
#pragma unroll
        for (int hh = 0; hh < 6; hh++) acc[k][hh] = 0.f;

    const float* zrow = z + (size_t)i * (Nn * 128);
    for (int cc = 0; cc < 8; cc++) {
        __syncthreads();
#pragma unroll
        for (int k = 0; k < 8; k++) {
            int f = t + k * 128;
            int jj = f >> 2, c4 = (f & 3) * 4;
            float4 zv = *(const float4*)&zrow[(size_t)(j0 + jj) * 128 + cc * 16 + c4];
            z_s[jj*17+c4+0] = zv.x; z_s[jj*17+c4+1] = zv.y;
            z_s[jj*17+c4+2] = zv.z; z_s[jj*17+c4+3] = zv.w;
        }
        __syncthreads();
#pragma unroll
        for (int c = 0; c < 16; c++) {
            float wv[6];
#pragma unroll
            for (int hh = 0; hh < 6; hh++) wv[hh] = wb_s[(cc*16+c)*12 + hg*6 + hh];
#pragma unroll
            for (int k = 0; k < 4; k++) {
                float zr = z_s[(jg*4+k)*17 + c];
#pragma unroll
                for (int hh = 0; hh < 6; hh++) acc[k][hh] += zr * wv[hh];
            }
        }
    }
#pragma unroll
    for (int hh = 0; hh < 6; hh++) {
        int h = hg * 6 + hh;
        float* ap = &g_a[(size_t)h * NNt + (size_t)i * Nn + j0 + jg*4];
        float4 v = *(float4*)ap;
        v.x += RS3 * acc[0][hh]; v.y += RS3 * acc[1][hh];
        v.z += RS3 * acc[2][hh]; v.w += RS3 * acc[3][hh];
        *(float4*)ap = v;
    }
}

/* --- K3: fused weighted softmax + o_pair = a.z  (z read #2, per-i) ------- */
__global__ __launch_bounds__(256) void k_soft_opair(const float* __restrict__ z,
                                                    const float* __restrict__ ss)
{
    __shared__ float la[12 * Nn];    /* logits -> attn -> reduce buf (36 KB) */
    __shared__ float wrow[Nn];
    int i = blockIdx.x, t = threadIdx.x;

    /* load logits */
    for (int idx = t; idx < 12 * Nn; idx += 256) {
        int h = idx / Nn, j = idx % Nn;
        la[idx] = g_a[(size_t)h * NNt + (size_t)i * Nn + j];
    }
    for (int j = t; j < Nn; j += 256)
        wrow[j] = expf(ss[(size_t)i * Nn + j]) - 0.99f;
    __syncthreads();

    /* weighted softmax: warp w handles rows h = w, w+8 */
    int wid = t / 32, lane = t % 32;
    for (int h = wid; h < 12; h += 8) {
        float m = -1e30f;
        for (int j = lane; j < Nn; j += 32) m = fmaxf(m, la[h * Nn + j]);
#pragma unroll
        for (int o = 16; o; o >>= 1) m = fmaxf(m, __shfl_xor_sync(0xffffffffu, m, o));
        float sum = 0.f;
        for (int j = lane; j < Nn; j += 32) {
            float e = expf(la[h * Nn + j] - m) * wrow[j];
            la[h * Nn + j] = e;
            sum += e;
        }
#pragma unroll
        for (int o = 16; o; o >>= 1) sum += __shfl_xor_sync(0xffffffffu, sum, o);
        float inv = 1.0f / sum;
        float* grow = &g_a[(size_t)h * NNt + (size_t)i * Nn];
        for (int j = lane; j < Nn; j += 32) {
            float v = la[h * Nn + j] * inv;
            la[h * Nn + j] = v;
            grow[j] = v;
        }
    }
    __syncthreads();

    /* o_pair: thread = (c-quad, j-group) ; 48 accumulators */
    int c4 = t % 32, jg = t / 32;
    const float4* zrow = (const float4*)(z + (size_t)i * Nn * 128);
    float acc[12][4];
#pragma unroll
    for (int h = 0; h < 12; h++)
#pragma unroll
        for (int c = 0; c < 4; c++) acc[h][c] = 0.f;

    for (int j = jg; j < Nn; j += 8) {
        float4 zv = __ldg(&zrow[j * 32 + c4]);
#pragma unroll
        for (int h = 0; h < 12; h++) {
            float av = la[h * Nn + j];
            acc[h][0] += av * zv.x;
            acc[h][1] += av * zv.y;
            acc[h][2] += av * zv.z;
            acc[h][3] += av * zv.w;
        }
    }

    /* reduce over 8 j-groups, 6 heads per pass (reuse la as scratch) */
#pragma unroll
    for (int pass = 0; pass < 2; pass++) {
        __syncthreads();
#pragma unroll
        for (int hh = 0; hh < 6; hh++)
#pragma unroll
            for (int c = 0; c < 4; c++)
                la[t * 24 + hh * 4 + c] = acc[pass * 6 + hh][c];
        __syncthreads();
        for (int idx = t; idx < 32 * 24; idx += 256) {
            int c4r = idx / 24, k = idx % 24;
            float sum = 0.f;
#pragma unroll
            for (int g = 0; g < 8; g++) sum += la[(g * 32 + c4r) * 24 + k];
            int h = pass * 6 + k / 4;
            int c = c4r * 4 + (k % 4);
            g_cat[(size_t)i * CATD + 576 + h * 128 + c] = sum;
        }
    }
}

/* ------ K4: o / o_pt as 12 GEMMs  768i x 40w x 768j  (64-i tiles) -------- */
__global__ __launch_bounds__(160) void k_out_ov()
{
    __shared__ float a_sT[16][66];
    __shared__ float vc_s[16][40];
    int i0 = blockIdx.x * 64, h = blockIdx.y;
    int t = threadIdx.x;
    int tx = t % 10, ty = t / 10;
    float acc[4][4];
#pragma unroll
    for (int a = 0; a < 4; a++)
#pragma unroll
        for (int b = 0; b < 4; b++) acc[a][b] = 0.f;

    const float* arow = &g_a[(size_t)h * NNt];
    const float* vcb  = &g_vc[(size_t)h * Nn * 48];

    for (int j0 = 0; j0 < Nn; j0 += 16) {
        __syncthreads();
        for (int idx = t; idx < 256; idx += 160) {
            int ii = idx / 4, q = idx % 4;
            float4 av = *(const float4*)&arow[(size_t)(i0 + ii) * Nn + j0 + q * 4];
            a_sT[q*4+0][ii] = av.x; a_sT[q*4+1][ii] = av.y;
            a_sT[q*4+2][ii] = av.z; a_sT[q*4+3][ii] = av.w;
        }
        for (int idx = t; idx < 640; idx += 160) {
            int jc = idx / 40, w = idx % 40;
            vc_s[jc][w] = vcb[(size_t)(j0 + jc) * 48 + w];
        }
        __syncthreads();
#pragma unroll
        for (int jc = 0; jc < 16; jc++) {
            float av[4], wv[4];
#pragma unroll
            for (int a = 0; a < 4; a++) av[a] = a_sT[jc][ty * 4 + a];
#pragma unroll
            for (int b = 0; b < 4; b++) wv[b] = vc_s[jc][tx * 4 + b];
#pragma unroll
            for (int a = 0; a < 4; a++)
#pragma unroll
                for (int b = 0; b < 4; b++) acc[a][b] += av[a] * wv[b];
        }
    }
#pragma unroll
    for (int a = 0; a < 4; a++) {
        int i = i0 + ty * 4 + a;
#pragma unroll
        for (int b = 0; b < 4; b++) {
            int w = tx * 4 + b;
            if (w < 16) g_cat[(size_t)i * CATD + h * 16 + w] = acc[a][b];
            else        g_ptg[(i * 12 + h) * 24 + (w - 16)]  = acc[a][b];
        }
    }
}

/* --------- K4b: frame-inverse rotation of o_pt + norms ------------------- */
__global__ __launch_bounds__(96) void k_ptfinish(const float* __restrict__ rot,
                                                 const float* __restrict__ trans)
{
    int i = blockIdx.x, t = threadIdx.x;
    int h = t / 8, p = t % 8;
    const float* pt = &g_ptg[(i * 12 + h) * 24 + p * 3];
    float gx = pt[0] - trans[i*3+0];
    float gy = pt[1] - trans[i*3+1];
    float gz = pt[2] - trans[i*3+2];
    const float* R = &rot[i*9];
    float lx = R[0]*gx + R[3]*gy + R[6]*gz;
    float ly = R[1]*gx + R[4]*gy + R[7]*gz;
    float lz = R[2]*gx + R[5]*gy + R[8]*gz;
    float nrm = sqrtf(lx*lx + ly*ly + lz*lz + 1e-8f);
    size_t base = (size_t)i * CATD;
    int hp = h * 8 + p;
    g_cat[base + 192 + hp] = lx;
    g_cat[base + 288 + hp] = ly;
    g_cat[base + 384 + hp] = lz;
    g_cat[base + 480 + hp] = nrm;
}

/* ------------------- K6: final GEMM 768 x 384 x 2112 --------------------- */
__global__ __launch_bounds__(256) void k_final(float* __restrict__ out,
                                               const float* __restrict__ W_out,
                                               const float* __restrict__ b_out)
{
    __shared__ float c_t[16][65];
    __shared__ float w_t[16][64];
    int o0 = blockIdx.x * 64, i0 = blockIdx.y * 64;
    int t = threadIdx.x;
    int tx = t % 16, ty = t / 16;
    float acc[4][4];
#pragma unroll
    for (int a = 0; a < 4; a++)
#pragma unroll
        for (int b = 0; b < 4; b++) acc[a][b] = 0.f;

    for (int k0 = 0; k0 < CATD; k0 += 16) {
        { int ii = t / 4, kc = (t % 4) * 4;
          float4 cv = *(const float4*)&g_cat[(size_t)(i0 + ii) * CATD + k0 + kc];
          c_t[kc+0][ii] = cv.x; c_t[kc+1][ii] = cv.y;
          c_t[kc+2][ii] = cv.z; c_t[kc+3][ii] = cv.w; }
        { int kc = t / 16, oo = (t % 16) * 4;
          *(float4*)&w_t[kc][oo] =
              *(const float4*)&W_out[(size_t)(k0 + kc) * 384 + o0 + oo]; }
        __syncthreads();
#pragma unroll
        for (int kc = 0; kc < 16; kc++) {
            float cv[4];
#pragma unroll
            for (int a = 0; a < 4; a++) cv[a] = c_t[kc][ty*4+a];
            float4 w4 = *(float4*)&w_t[kc][tx*4];
            float wv[4] = {w4.x, w4.y, w4.z, w4.w};
#pragma unroll
            for (int a = 0; a < 4; a++)
#pragma unroll
                for (int b = 0; b < 4; b++) acc[a][b] += cv[a] * wv[b];
        }
        __syncthreads();
    }
#pragma unroll
    for (int a = 0; a < 4; a++) {
        float4 o4;
        o4.x = acc[a][0] + b_out[o0 + tx*4 + 0];
        o4.y = acc[a][1] + b_out[o0 + tx*4 + 1];
        o4.z = acc[a][2] + b_out[o0 + tx*4 + 2];
        o4.w = acc[a][3] + b_out[o0 + tx*4 + 3];
        *(float4*)&out[(size_t)(i0 + ty*4 + a) * 384 + o0 + tx*4] = o4;
    }
}

/* ------------------------------- launch ---------------------------------- */
extern "C" void kernel_launch(void* const* d_in, const int* in_sizes, int n_in,
                              void* d_out, int out_size)
{
    const float* s     = (const float*)d_in[0];
    const float* z     = (const float*)d_in[1];
    const float* rot   = (const float*)d_in[2];
    const float* trans = (const float*)d_in[3];
    const float* mask  = (const float*)d_in[4];
    const float* ss    = (const float*)d_in[5];
    const float* W_q   = (const float*)d_in[6];
    const float* b_q   = (const float*)d_in[7];
    const float* W_kv  = (const float*)d_in[8];
    const float* b_kv  = (const float*)d_in[9];
    const float* W_qp  = (const float*)d_in[10];
    const float* b_qp  = (const float*)d_in[11];
    const float* W_kvp = (const float*)d_in[12];
    const float* b_kvp = (const float*)d_in[13];
    const float* W_b   = (const float*)d_in[14];
    const float* b_b   = (const float*)d_in[15];
    const float* hwts  = (const float*)d_in[16];
    const float* W_out = (const float*)d_in[17];
    const float* b_out = (const float*)d_in[18];
    float* out = (float*)d_out;

    k_pack<<<(384 * PROJ + 255) / 256, 256>>>(W_q, W_kv, W_qp, W_kvp,
                                              b_q, b_kv, b_qp, b_kvp);
    { dim3 g(PROJ / 64, Nn / 64); k_proj_gemm<<<g, 256>>>(s); }
    k_reshape<<<Nn, 192>>>(rot, trans);
    { dim3 g(Nn / 64, Nn / 64, 12); k_logits<<<g, 256>>>(mask, hwts, b_b); }
    { dim3 g(Nn / 256, Nn); k_bias_add<<<g, 128>>>(z, W_b); }
    k_soft_opair<<<Nn, 256>>>(z, ss);
    { dim3 g(Nn / 64, 12); k_out_ov<<<g, 160>>>(); }
    k_ptfinish<<<Nn, 96>>>(rot, trans);
    { dim3 g(384 / 64, Nn / 64); k_final<<<g, 256>>>(out, W_out, b_out); }
}